// round 8
// baseline (speedup 1.0000x reference)
#include <cuda_runtime.h>
#include <cuda_bf16.h>
#include <cstdint>

// ============================================================
// LoRALinear on base sm_103 (no 'a' features):
//   out = (x @ signs^T) * scale + 2 * ((x@A^T) @ B^T)
// Path: int8 double-digit IMMA m16n8k32.
//   x ~= (s_m/127) * (a + b/254), a,b int8; signs exact int8.
//   out_base = (s_m/127)*(accA + accB/254)*scale_n
//   LoRA folded as 3 bf16 m16n8k16 steps onto the folded f32 acc.
// ============================================================

#define DINLINE __device__ __forceinline__

// ---------------- scratch (device globals) ----------------
__device__ int8_t        g_xhi[8192u * 4096u];   // 32 MB
__device__ int8_t        g_xlo[8192u * 4096u];   // 32 MB
__device__ int8_t        g_s8 [4096u * 4096u];   // 16 MB signs
__device__ float         g_s  [8192];            // per-row scale of x
__device__ float         g_t  [8192 * 16];       // t = x @ A^T
__device__ __nv_bfloat16 g_tA [8192 * 48];       // [t_hi | t_lo | t_hi]
__device__ __nv_bfloat16 g_tB [4096 * 48];       // [B''hi | B''hi | B''lo], B''=2B/scale

// ---------------- PTX helpers ----------------
DINLINE uint32_t smem_u32(const void* p) {
    uint32_t a;
    asm("{ .reg .u64 t; cvta.to.shared.u64 t, %1; cvt.u32.u64 %0, t; }"
        : "=r"(a) : "l"(p));
    return a;
}

DINLINE void cpa16(uint32_t s, const void* g) {
    asm volatile("cp.async.cg.shared.global [%0], [%1], 16;" :: "r"(s), "l"(g));
}
#define CP_COMMIT()  asm volatile("cp.async.commit_group;" ::: "memory")
#define CP_WAIT(n)   asm volatile("cp.async.wait_group %0;" :: "n"(n) : "memory")

#define LDSM4(r0, r1, r2, r3, addr)                                              \
    asm volatile("ldmatrix.sync.aligned.m8n8.x4.shared.b16 {%0,%1,%2,%3}, [%4];" \
                 : "=r"(r0), "=r"(r1), "=r"(r2), "=r"(r3) : "r"(addr))

#define IMMA16832(d, a, b)                                                       \
    asm volatile("mma.sync.aligned.m16n8k32.row.col.s32.s8.s8.s32 "              \
                 "{%0,%1,%2,%3}, {%4,%5,%6,%7}, {%8,%9}, {%0,%1,%2,%3};"         \
                 : "+r"((d)[0]), "+r"((d)[1]), "+r"((d)[2]), "+r"((d)[3])        \
                 : "r"((a)[0]), "r"((a)[1]), "r"((a)[2]), "r"((a)[3]),           \
                   "r"((b)[0]), "r"((b)[1]))

#define MMA16816F(d, a, b)                                                       \
    asm volatile("mma.sync.aligned.m16n8k16.row.col.f32.bf16.bf16.f32 "          \
                 "{%0,%1,%2,%3}, {%4,%5,%6,%7}, {%8,%9}, {%0,%1,%2,%3};"         \
                 : "+f"((d)[0]), "+f"((d)[1]), "+f"((d)[2]), "+f"((d)[3])        \
                 : "r"((a)[0]), "r"((a)[1]), "r"((a)[2]), "r"((a)[3]),           \
                   "r"((b)[0]), "r"((b)[1]))

DINLINE uint32_t pack4b(int a0, int a1, int a2, int a3) {
    return (uint32_t)(a0 & 0xFF) | ((uint32_t)(a1 & 0xFF) << 8) |
           ((uint32_t)(a2 & 0xFF) << 16) | ((uint32_t)(a3 & 0xFF) << 24);
}

// ---------------- kernel 1: per-row quantize x -> (a, b) int8 + s ----------
__global__ __launch_bounds__(256) void quantize_x_kernel(const float* __restrict__ x) {
    __shared__ float red[8];
    const int row = blockIdx.x, tid = threadIdx.x;
    const float4* xr = (const float4*)(x + (size_t)row * 4096);

    float4 v[4];
    float m = 0.f;
    #pragma unroll
    for (int i = 0; i < 4; i++) {
        v[i] = xr[tid + 256 * i];
        m = fmaxf(m, fmaxf(fmaxf(fabsf(v[i].x), fabsf(v[i].y)),
                           fmaxf(fabsf(v[i].z), fabsf(v[i].w))));
    }
    #pragma unroll
    for (int o = 16; o > 0; o >>= 1) m = fmaxf(m, __shfl_xor_sync(~0u, m, o));
    if ((tid & 31) == 0) red[tid >> 5] = m;
    __syncthreads();
    if (tid < 32) {
        float mm = (tid < 8) ? red[tid] : 0.f;
        #pragma unroll
        for (int o = 4; o > 0; o >>= 1) mm = fmaxf(mm, __shfl_xor_sync(~0u, mm, o));
        if (tid == 0) { red[0] = (mm > 0.f ? mm : 1.f); if (row >= 0) g_s[row] = red[0]; }
    }
    __syncthreads();
    const float q = 127.0f / red[0];

    uint32_t* hi = (uint32_t*)(g_xhi + (size_t)row * 4096);
    uint32_t* lo = (uint32_t*)(g_xlo + (size_t)row * 4096);
    #pragma unroll
    for (int i = 0; i < 4; i++) {
        float c[4] = {v[i].x, v[i].y, v[i].z, v[i].w};
        int a[4], b[4];
        #pragma unroll
        for (int j = 0; j < 4; j++) {
            float qa = rintf(c[j] * q);
            a[j] = (int)qa;
            b[j] = (int)rintf((c[j] * q - qa) * 254.0f);
        }
        hi[tid + 256 * i] = pack4b(a[0], a[1], a[2], a[3]);
        lo[tid + 256 * i] = pack4b(b[0], b[1], b[2], b[3]);
    }
}

// ---------------- kernel 2: signs f32 -> int8 ----------------
__global__ __launch_bounds__(256) void signs_s8_kernel(const float* __restrict__ s) {
    size_t base = ((size_t)blockIdx.x * 256 + threadIdx.x) * 16;
    uint32_t w[4];
    #pragma unroll
    for (int i = 0; i < 4; i++) {
        float4 v = *(const float4*)(s + base + i * 4);
        w[i] = pack4b(v.x > 0.f ? 1 : -1, v.y > 0.f ? 1 : -1,
                      v.z > 0.f ? 1 : -1, v.w > 0.f ? 1 : -1);
    }
    *(uint4*)(g_s8 + base) = make_uint4(w[0], w[1], w[2], w[3]);
}

// ---------------- kernel 3: t[8192,16] = x @ lora_A^T (fp32) ----------------
__global__ __launch_bounds__(256) void lora_t_kernel(const float* __restrict__ x,
                                                     const float* __restrict__ A) {
    __shared__ float4 As4[16 * 128];
    __shared__ float ts[64 * 16];
    int tid = threadIdx.x, w = tid >> 5, lane = tid & 31;

    #pragma unroll
    for (int j = 0; j < 4; j++) ts[tid * 4 + j] = 0.f;

    for (int kc = 0; kc < 4096; kc += 512) {
        __syncthreads();
        #pragma unroll
        for (int i = 0; i < 8; i++) {
            int idx = tid + 256 * i;
            int r = idx >> 7, q = idx & 127;
            As4[idx] = *(const float4*)(A + (size_t)r * 4096 + kc + q * 4);
        }
        __syncthreads();
        for (int rr = 0; rr < 8; rr++) {
            int row = blockIdx.x * 64 + w * 8 + rr;
            const float4* xr = (const float4*)(x + (size_t)row * 4096 + kc);
            float acc[16];
            #pragma unroll
            for (int r = 0; r < 16; r++) acc[r] = 0.f;
            #pragma unroll
            for (int i = 0; i < 4; i++) {
                int kq = lane + i * 32;
                float4 xv = xr[kq];
                #pragma unroll
                for (int r = 0; r < 16; r++) {
                    float4 av = As4[r * 128 + kq];
                    acc[r] += xv.x * av.x + xv.y * av.y + xv.z * av.z + xv.w * av.w;
                }
            }
            #pragma unroll
            for (int r = 0; r < 16; r++) {
                float v = acc[r];
                v += __shfl_xor_sync(0xFFFFFFFFu, v, 16);
                v += __shfl_xor_sync(0xFFFFFFFFu, v, 8);
                v += __shfl_xor_sync(0xFFFFFFFFu, v, 4);
                v += __shfl_xor_sync(0xFFFFFFFFu, v, 2);
                v += __shfl_xor_sync(0xFFFFFFFFu, v, 1);
                if (lane == 0) ts[(w * 8 + rr) * 16 + r] += v;
            }
        }
    }
    __syncthreads();
    #pragma unroll
    for (int j = 0; j < 4; j++)
        g_t[(size_t)blockIdx.x * 1024 + tid * 4 + j] = ts[tid * 4 + j];
}

// ---------------- kernel 4: pack t -> bf16 [hi | lo | hi] (48/row) ----------
__global__ __launch_bounds__(256) void t_pack_kernel() {
    int row = blockIdx.x * 256 + threadIdx.x;          // < 8192
    const float* t = g_t + (size_t)row * 16;
    __align__(16) __nv_bfloat16 o[48];
    #pragma unroll
    for (int r = 0; r < 16; r++) {
        float f = t[r];
        __nv_bfloat16 h = __float2bfloat16(f);
        __nv_bfloat16 l = __float2bfloat16(f - __bfloat162float(h));
        o[r] = h; o[16 + r] = l; o[32 + r] = h;
    }
    uint4* dst = (uint4*)(g_tA + (size_t)row * 48);
    const uint4* src = (const uint4*)o;
    #pragma unroll
    for (int j = 0; j < 6; j++) dst[j] = src[j];
}

// ---------------- kernel 5: pack B'' = 2*lora_B/scale -> [hi | hi | lo] -----
__global__ __launch_bounds__(256) void b_pack_kernel(const float* __restrict__ loraB,
                                                     const float* __restrict__ scale) {
    int n = blockIdx.x * 256 + threadIdx.x;            // < 4096
    float inv = 2.0f / scale[n];
    __align__(16) __nv_bfloat16 o[48];
    #pragma unroll
    for (int r = 0; r < 16; r++) {
        float v = loraB[(size_t)n * 16 + r] * inv;
        __nv_bfloat16 h = __float2bfloat16(v);
        __nv_bfloat16 l = __float2bfloat16(v - __bfloat162float(h));
        o[r] = h; o[16 + r] = h; o[32 + r] = l;
    }
    uint4* dst = (uint4*)(g_tB + (size_t)n * 48);
    const uint4* src = (const uint4*)o;
    #pragma unroll
    for (int j = 0; j < 6; j++) dst[j] = src[j];
}

// ---------------- kernel 6: main int8 IMMA GEMM ----------------
// CTA 128x128, 512 threads (16 warps, warp tile 32x32).
// K-chunk 64 bytes. Stage: A_hi 128x80 | A_lo 128x80 | B 128x80 = 30720 B.
// 4 stages = 122880 B. Row pitch 80 B => ldmatrix conflict-free, no swizzle.
static constexpr int APITCH = 80;
static constexpr int STAGE  = 3 * 128 * APITCH;        // 30720
static constexpr int NSTAGE = 4;
static constexpr int SMEM_TOTAL = NSTAGE * STAGE;      // 122880
static constexpr int LPITCH = 112;                     // epilogue bf16 tiles (96B rows)

DINLINE void issue_chunk(int m0, int n0, int c, uint32_t su, int tid) {
    int row = tid >> 2, g = tid & 3;                   // 512 threads -> 128 rows x 4
    uint32_t off = (uint32_t)(row * APITCH + g * 16);
    size_t ks = (size_t)c * 64 + g * 16;
    cpa16(su + off,                 g_xhi + ((size_t)(m0 + row)) * 4096 + ks);
    cpa16(su + 128 * APITCH + off,  g_xlo + ((size_t)(m0 + row)) * 4096 + ks);
    cpa16(su + 256 * APITCH + off,  g_s8  + ((size_t)(n0 + row)) * 4096 + ks);
    CP_COMMIT();
}

__global__ __launch_bounds__(512, 1) void lora_gemm_kernel(
    const float* __restrict__ scale, float* __restrict__ out) {
    extern __shared__ __align__(1024) char sm[];
    const uint32_t sbase = smem_u32(sm);
    const int tid = threadIdx.x, wid = tid >> 5, l = tid & 31;
    const int warp_m = wid >> 2, warp_n = wid & 3;     // 4x4 warps over 128x128
    const int n0 = blockIdx.x * 128, m0 = blockIdx.y * 128;

    int accA[2][4][4], accB[2][4][4];
    #pragma unroll
    for (int i = 0; i < 2; i++)
        #pragma unroll
        for (int n = 0; n < 4; n++)
            #pragma unroll
            for (int j = 0; j < 4; j++) { accA[i][n][j] = 0; accB[i][n][j] = 0; }

    // ldmatrix lane-address components (row pitch 80)
    const uint32_t aoff = (uint32_t)((warp_m * 32 + ((l >> 3) & 1) * 8 + (l & 7)) * APITCH)
                        + (uint32_t)(l >> 4) * 16;
    const uint32_t boff = (uint32_t)((warp_n * 32 + ((l >> 4) << 3) + (l & 7)) * APITCH)
                        + (uint32_t)((l >> 3) & 1) * 16;

    issue_chunk(m0, n0, 0, sbase + 0 * STAGE, tid);
    issue_chunk(m0, n0, 1, sbase + 1 * STAGE, tid);
    issue_chunk(m0, n0, 2, sbase + 2 * STAGE, tid);

    for (int c = 0; c < 64; c++) {
        __syncthreads();                               // stage reuse guard
        if (c + 3 < 64) issue_chunk(m0, n0, c + 3, sbase + ((c + 3) & 3) * STAGE, tid);
        else            CP_COMMIT();                   // keep group count consistent
        CP_WAIT(3);
        __syncthreads();

        const uint32_t As = sbase + (uint32_t)(c & 3) * STAGE;
        const uint32_t Ls = As + 128 * APITCH;
        const uint32_t Bs = As + 256 * APITCH;

        #pragma unroll
        for (int kk = 0; kk < 2; kk++) {
            uint32_t bb[4][2];
            #pragma unroll
            for (int j = 0; j < 2; j++) {
                LDSM4(bb[2 * j][0], bb[2 * j][1], bb[2 * j + 1][0], bb[2 * j + 1][1],
                      Bs + boff + (uint32_t)(j * 16 * APITCH) + (uint32_t)(kk * 32));
            }
            #pragma unroll
            for (int i = 0; i < 2; i++) {
                uint32_t ah[4];
                LDSM4(ah[0], ah[1], ah[2], ah[3],
                      As + aoff + (uint32_t)(i * 16 * APITCH) + (uint32_t)(kk * 32));
                #pragma unroll
                for (int n = 0; n < 4; n++) IMMA16832(accA[i][n], ah, bb[n]);
            }
            #pragma unroll
            for (int i = 0; i < 2; i++) {
                uint32_t al[4];
                LDSM4(al[0], al[1], al[2], al[3],
                      Ls + aoff + (uint32_t)(i * 16 * APITCH) + (uint32_t)(kk * 32));
                #pragma unroll
                for (int n = 0; n < 4; n++) IMMA16832(accB[i][n], al, bb[n]);
            }
        }
    }

    // -------- epilogue --------
    __syncthreads();
    // lora tiles (bf16, 96B rows, pitch 112) into stage0; scales after them
    {
        #pragma unroll
        for (int r = 0; r < 3; r++) {
            int idx = tid + 512 * r;                   // < 1536
            if (idx < 768) {
                int row = idx / 6, g = idx % 6;
                cpa16(sbase + row * LPITCH + g * 16,
                      g_tA + (size_t)(m0 + row) * 48 + g * 8);
            } else {
                int idx2 = idx - 768;
                int row = idx2 / 6, g = idx2 % 6;
                cpa16(sbase + 14336 + row * LPITCH + g * 16,
                      g_tB + (size_t)(n0 + row) * 48 + g * 8);
            }
        }
        CP_COMMIT();
    }
    float* sS = (float*)(sm + 28672);                  // scale[n0..n0+127]
    float* sR = (float*)(sm + 28672 + 512);            // g_s[m0..m0+127]
    if (tid < 128)       sS[tid] = scale[n0 + tid];
    else if (tid < 256)  sR[tid - 128] = g_s[m0 + tid - 128];
    CP_WAIT(0);
    __syncthreads();

    // fold int accumulators into f32
    const float c1 = 1.0f / 127.0f;
    const float c2 = 1.0f / (127.0f * 254.0f);
    float facc[2][4][4];
    #pragma unroll
    for (int i = 0; i < 2; i++) {
        int rl = warp_m * 32 + i * 16 + (l >> 2);
        float s_lo = sR[rl], s_hi = sR[rl + 8];
        #pragma unroll
        for (int n = 0; n < 4; n++) {
            facc[i][n][0] = s_lo * ((float)accA[i][n][0] * c1 + (float)accB[i][n][0] * c2);
            facc[i][n][1] = s_lo * ((float)accA[i][n][1] * c1 + (float)accB[i][n][1] * c2);
            facc[i][n][2] = s_hi * ((float)accA[i][n][2] * c1 + (float)accB[i][n][2] * c2);
            facc[i][n][3] = s_hi * ((float)accA[i][n][3] * c1 + (float)accB[i][n][3] * c2);
        }
    }

    // lora: 3 bf16 k16 steps onto facc
    const uint32_t aoffL = (uint32_t)((warp_m * 32 + ((l >> 3) & 1) * 8 + (l & 7)) * LPITCH)
                         + (uint32_t)(l >> 4) * 16;
    const uint32_t boffL = (uint32_t)((warp_n * 32 + ((l >> 4) << 3) + (l & 7)) * LPITCH)
                         + (uint32_t)((l >> 3) & 1) * 16;
    #pragma unroll
    for (int kk = 0; kk < 3; kk++) {
        uint32_t bb[4][2];
        #pragma unroll
        for (int j = 0; j < 2; j++) {
            LDSM4(bb[2 * j][0], bb[2 * j][1], bb[2 * j + 1][0], bb[2 * j + 1][1],
                  sbase + 14336 + boffL + (uint32_t)(j * 16 * LPITCH) + (uint32_t)(kk * 32));
        }
        #pragma unroll
        for (int i = 0; i < 2; i++) {
            uint32_t ah[4];
            LDSM4(ah[0], ah[1], ah[2], ah[3],
                  sbase + aoffL + (uint32_t)(i * 16 * LPITCH) + (uint32_t)(kk * 32));
            #pragma unroll
            for (int n = 0; n < 4; n++) MMA16816F(facc[i][n], ah, bb[n]);
        }
    }

    // scale by per-column scale and store
    #pragma unroll
    for (int i = 0; i < 2; i++) {
        int r0 = m0 + warp_m * 32 + i * 16 + (l >> 2);
        #pragma unroll
        for (int n = 0; n < 4; n++) {
            int cl = warp_n * 32 + n * 8 + (l & 3) * 2;
            float s0 = sS[cl], s1 = sS[cl + 1];
            float2 o0 = make_float2(facc[i][n][0] * s0, facc[i][n][1] * s1);
            float2 o1 = make_float2(facc[i][n][2] * s0, facc[i][n][3] * s1);
            *(float2*)(out + (size_t)r0 * 4096 + n0 + cl) = o0;
            *(float2*)(out + (size_t)(r0 + 8) * 4096 + n0 + cl) = o1;
        }
    }
}

// ---------------- launcher ----------------
extern "C" void kernel_launch(void* const* d_in, const int* in_sizes, int n_in,
                              void* d_out, int out_size) {
    const float* x      = (const float*)d_in[0];
    const float* signs  = (const float*)d_in[1];
    const float* scale  = (const float*)d_in[2];
    const float* lora_A = (const float*)d_in[3];
    const float* lora_B = (const float*)d_in[4];
    float* out = (float*)d_out;

    quantize_x_kernel<<<8192, 256>>>(x);
    signs_s8_kernel<<<4096, 256>>>(signs);
    lora_t_kernel<<<128, 256>>>(x, lora_A);
    t_pack_kernel<<<32, 256>>>();
    b_pack_kernel<<<16, 256>>>(lora_B, scale);

    cudaFuncSetAttribute(lora_gemm_kernel,
                         cudaFuncAttributeMaxDynamicSharedMemorySize, SMEM_TOTAL);
    lora_gemm_kernel<<<dim3(32, 64), 512, SMEM_TOTAL>>>(scale, out);
}

// round 11
// speedup vs baseline: 3.8418x; 3.8418x over previous
#include <cuda_runtime.h>
#include <cuda_fp16.h>
#include <cstdint>

// ============================================================
// LoRALinear on base sm_103 (no 'a' features):
//   out = (x @ signs^T) * scale + 2 * ((x@A^T) @ B^T)
// Path: SINGLE-PASS fp16 HMMA m16n8k16 (fp16 = 11 mantissa bits ->
// norm rel_err ~2^-12 ~ 1.5e-4 < 1e-3). signs exact in fp16.
// LoRA folded as 3 fp16 k16 steps (hi/lo split, ~exact).
// ============================================================

#define DINLINE __device__ __forceinline__

// ---------------- scratch (device globals) ----------------
__device__ __half g_xh[8192u * 4096u];   // 64 MB  x in fp16
__device__ __half g_sh[4096u * 4096u];   // 32 MB  signs in fp16 (exact)
__device__ float  g_t [8192 * 16];       // t = x @ A^T (fp32)
__device__ __half g_tA[8192 * 48];       // [t_hi | t_lo | t_hi]
__device__ __half g_tB[4096 * 48];       // [B''hi | B''hi | B''lo], B''=2B/scale

// ---------------- PTX helpers ----------------
DINLINE uint32_t smem_u32(const void* p) {
    uint32_t a;
    asm("{ .reg .u64 t; cvta.to.shared.u64 t, %1; cvt.u32.u64 %0, t; }"
        : "=r"(a) : "l"(p));
    return a;
}

DINLINE void cpa16(uint32_t s, const void* g) {
    asm volatile("cp.async.cg.shared.global [%0], [%1], 16;" :: "r"(s), "l"(g));
}
#define CP_COMMIT()  asm volatile("cp.async.commit_group;" ::: "memory")
#define CP_WAIT(n)   asm volatile("cp.async.wait_group %0;" :: "n"(n) : "memory")

#define LDSM4(r0, r1, r2, r3, addr)                                              \
    asm volatile("ldmatrix.sync.aligned.m8n8.x4.shared.b16 {%0,%1,%2,%3}, [%4];" \
                 : "=r"(r0), "=r"(r1), "=r"(r2), "=r"(r3) : "r"(addr))

#define MMA16816H(d, a, b)                                                       \
    asm volatile("mma.sync.aligned.m16n8k16.row.col.f32.f16.f16.f32 "            \
                 "{%0,%1,%2,%3}, {%4,%5,%6,%7}, {%8,%9}, {%0,%1,%2,%3};"         \
                 : "+f"((d)[0]), "+f"((d)[1]), "+f"((d)[2]), "+f"((d)[3])        \
                 : "r"((a)[0]), "r"((a)[1]), "r"((a)[2]), "r"((a)[3]),           \
                   "r"((b)[0]), "r"((b)[1]))

// ---------------- kernel 1: x f32 -> fp16 ----------------
__global__ __launch_bounds__(256) void x_h_kernel(const float* __restrict__ x) {
    size_t base = ((size_t)blockIdx.x * 256 + threadIdx.x) * 8;
    float4 a = *(const float4*)(x + base);
    float4 b = *(const float4*)(x + base + 4);
    __half2 p0 = __floats2half2_rn(a.x, a.y);
    __half2 p1 = __floats2half2_rn(a.z, a.w);
    __half2 p2 = __floats2half2_rn(b.x, b.y);
    __half2 p3 = __floats2half2_rn(b.z, b.w);
    uint4 o;
    o.x = *(uint32_t*)&p0; o.y = *(uint32_t*)&p1;
    o.z = *(uint32_t*)&p2; o.w = *(uint32_t*)&p3;
    *(uint4*)(g_xh + base) = o;
}

// ---------------- kernel 2: signs f32 -> fp16 (exact) ----------------
__global__ __launch_bounds__(256) void s_h_kernel(const float* __restrict__ s) {
    size_t base = ((size_t)blockIdx.x * 256 + threadIdx.x) * 8;
    float4 a = *(const float4*)(s + base);
    float4 b = *(const float4*)(s + base + 4);
    __half2 p0 = __floats2half2_rn(a.x, a.y);
    __half2 p1 = __floats2half2_rn(a.z, a.w);
    __half2 p2 = __floats2half2_rn(b.x, b.y);
    __half2 p3 = __floats2half2_rn(b.z, b.w);
    uint4 o;
    o.x = *(uint32_t*)&p0; o.y = *(uint32_t*)&p1;
    o.z = *(uint32_t*)&p2; o.w = *(uint32_t*)&p3;
    *(uint4*)(g_sh + base) = o;
}

// ---------------- kernel 3: t[8192,16] = x @ lora_A^T (fp32) ----------------
__global__ __launch_bounds__(256) void lora_t_kernel(const float* __restrict__ x,
                                                     const float* __restrict__ A) {
    __shared__ float4 As4[16 * 128];
    __shared__ float ts[64 * 16];
    int tid = threadIdx.x, w = tid >> 5, lane = tid & 31;

    #pragma unroll
    for (int j = 0; j < 4; j++) ts[tid * 4 + j] = 0.f;

    for (int kc = 0; kc < 4096; kc += 512) {
        __syncthreads();
        #pragma unroll
        for (int i = 0; i < 8; i++) {
            int idx = tid + 256 * i;
            int r = idx >> 7, q = idx & 127;
            As4[idx] = *(const float4*)(A + (size_t)r * 4096 + kc + q * 4);
        }
        __syncthreads();
        for (int rr = 0; rr < 8; rr++) {
            int row = blockIdx.x * 64 + w * 8 + rr;
            const float4* xr = (const float4*)(x + (size_t)row * 4096 + kc);
            float acc[16];
            #pragma unroll
            for (int r = 0; r < 16; r++) acc[r] = 0.f;
            #pragma unroll
            for (int i = 0; i < 4; i++) {
                int kq = lane + i * 32;
                float4 xv = xr[kq];
                #pragma unroll
                for (int r = 0; r < 16; r++) {
                    float4 av = As4[r * 128 + kq];
                    acc[r] += xv.x * av.x + xv.y * av.y + xv.z * av.z + xv.w * av.w;
                }
            }
            #pragma unroll
            for (int r = 0; r < 16; r++) {
                float v = acc[r];
                v += __shfl_xor_sync(0xFFFFFFFFu, v, 16);
                v += __shfl_xor_sync(0xFFFFFFFFu, v, 8);
                v += __shfl_xor_sync(0xFFFFFFFFu, v, 4);
                v += __shfl_xor_sync(0xFFFFFFFFu, v, 2);
                v += __shfl_xor_sync(0xFFFFFFFFu, v, 1);
                if (lane == 0) ts[(w * 8 + rr) * 16 + r] += v;
            }
        }
    }
    __syncthreads();
    #pragma unroll
    for (int j = 0; j < 4; j++)
        g_t[(size_t)blockIdx.x * 1024 + tid * 4 + j] = ts[tid * 4 + j];
}

// ---------------- kernel 4: pack t -> fp16 [hi | lo | hi] (48/row) ----------
__global__ __launch_bounds__(256) void t_pack_kernel() {
    int row = blockIdx.x * 256 + threadIdx.x;          // < 8192
    const float* t = g_t + (size_t)row * 16;
    __align__(16) __half o[48];
    #pragma unroll
    for (int r = 0; r < 16; r++) {
        float f = t[r];
        __half h = __float2half_rn(f);
        __half l = __float2half_rn(f - __half2float(h));
        o[r] = h; o[16 + r] = l; o[32 + r] = h;
    }
    uint4* dst = (uint4*)(g_tA + (size_t)row * 48);
    const uint4* src = (const uint4*)o;
    #pragma unroll
    for (int j = 0; j < 6; j++) dst[j] = src[j];
}

// ---------------- kernel 5: pack B'' = 2*lora_B/scale -> [hi | hi | lo] -----
__global__ __launch_bounds__(256) void b_pack_kernel(const float* __restrict__ loraB,
                                                     const float* __restrict__ scale) {
    int n = blockIdx.x * 256 + threadIdx.x;            // < 4096
    float inv = 2.0f / scale[n];
    __align__(16) __half o[48];
    #pragma unroll
    for (int r = 0; r < 16; r++) {
        float v = loraB[(size_t)n * 16 + r] * inv;
        __half h = __float2half_rn(v);
        __half l = __float2half_rn(v - __half2float(h));
        o[r] = h; o[16 + r] = h; o[32 + r] = l;
    }
    uint4* dst = (uint4*)(g_tB + (size_t)n * 48);
    const uint4* src = (const uint4*)o;
    #pragma unroll
    for (int j = 0; j < 6; j++) dst[j] = src[j];
}

// ---------------- kernel 6: main fp16 HMMA GEMM ----------------
// CTA 128x128, 256 thr (8 warps: warp_m = wid>>1 over 32 rows, warp_n = wid&1
// over 64 cols). K-chunk 64 fp16. Stage: A 128x64 fp16 (16 KB, 128B rows,
// XOR swizzle) + B same = 32 KB. 3 stages = 96 KB -> 2 CTAs/SM.
static constexpr int STAGE = 32768;
static constexpr int NSTAGE = 3;
static constexpr int SMEM_TOTAL = NSTAGE * STAGE;      // 98304

DINLINE void issue_normal(int m0, int n0, int c, uint32_t su, int tid) {
    #pragma unroll
    for (int i = 0; i < 4; i++) {
        int idx = tid + 256 * i;                       // < 1024 x 16B (A)
        int row = idx >> 3, g = idx & 7;
        uint32_t off = (uint32_t)(row * 128 + g * 16) ^ (uint32_t)((row & 7) << 4);
        cpa16(su + off,         g_xh + (size_t)(m0 + row) * 4096 + c * 64 + g * 8);
        cpa16(su + 16384 + off, g_sh + (size_t)(n0 + row) * 4096 + c * 64 + g * 8);
    }
    CP_COMMIT();
}

DINLINE void issue_lora(int m0, int n0, uint32_t su, int tid) {
    #pragma unroll
    for (int i = 0; i < 3; i++) {
        int idx = tid + 256 * i;                       // < 768 x 16B each matrix
        int row = idx / 6, g = idx % 6;
        uint32_t off = (uint32_t)(row * 128 + g * 16) ^ (uint32_t)((row & 7) << 4);
        cpa16(su + off,         g_tA + (size_t)(m0 + row) * 48 + g * 8);
        cpa16(su + 16384 + off, g_tB + (size_t)(n0 + row) * 48 + g * 8);
    }
    CP_COMMIT();
}

__global__ __launch_bounds__(256, 2) void lora_gemm_kernel(
    const float* __restrict__ scale, float* __restrict__ out) {
    extern __shared__ __align__(1024) char sm[];
    const uint32_t sbase = smem_u32(sm);
    const int tid = threadIdx.x, wid = tid >> 5, l = tid & 31;
    const int warp_m = wid >> 1, warp_n = wid & 1;
    const int n0 = blockIdx.x * 128, m0 = blockIdx.y * 128;

    float acc[2][8][4];
    #pragma unroll
    for (int i = 0; i < 2; i++)
        #pragma unroll
        for (int n = 0; n < 8; n++)
            #pragma unroll
            for (int j = 0; j < 4; j++) acc[i][n][j] = 0.f;

    // lane constants (verified by the R2 passing run)
    const uint32_t brow  = (uint32_t)(l & 15);
    const uint32_t bhalf = (uint32_t)(l >> 4);
    const uint32_t sx    = (uint32_t)((l & 7) << 4);

    issue_normal(m0, n0, 0, sbase + 0 * STAGE, tid);
    issue_normal(m0, n0, 1, sbase + 1 * STAGE, tid);
    issue_normal(m0, n0, 2, sbase + 2 * STAGE, tid);

    // chunks 0..63 normal + chunk 64 = lora (3 k16 steps)
    for (int c = 0; c <= 64; c++) {
        CP_WAIT(2);
        __syncthreads();

        const int st = c % 3;
        const uint32_t As = sbase + (uint32_t)st * STAGE;
        const uint32_t Bs = As + 16384;
        const int nk16 = (c < 64) ? 4 : 3;

        for (int k16 = 0; k16 < nk16; k16++) {
            uint32_t bb[8][2];
            #pragma unroll
            for (int g = 0; g < 4; g++) {
                uint32_t addr = Bs +
                    (((uint32_t)((warp_n * 64 + g * 16 + brow) * 128)
                      + (uint32_t)(k16 * 32) + bhalf * 16) ^ sx);
                LDSM4(bb[2 * g][0], bb[2 * g + 1][0],
                      bb[2 * g][1], bb[2 * g + 1][1], addr);
            }
            #pragma unroll
            for (int i = 0; i < 2; i++) {
                uint32_t addr = As +
                    (((uint32_t)((warp_m * 32 + i * 16 + brow) * 128)
                      + (uint32_t)(k16 * 32) + bhalf * 16) ^ sx);
                uint32_t ah[4];
                LDSM4(ah[0], ah[1], ah[2], ah[3], addr);
                #pragma unroll
                for (int n = 0; n < 8; n++) MMA16816H(acc[i][n], ah, bb[n]);
            }
        }
        __syncthreads();

        // refill the stage just consumed
        if (c + 3 < 64)       issue_normal(m0, n0, c + 3, sbase + (uint32_t)st * STAGE, tid);
        else if (c + 3 == 64) issue_lora(m0, n0, sbase + (uint32_t)st * STAGE, tid);
        else                  CP_COMMIT();             // keep group arithmetic exact
    }

    // ---- epilogue: out = acc * scale[col] ----
    float* sS = (float*)sm;
    if (tid < 128) sS[tid] = scale[n0 + tid];
    __syncthreads();

    #pragma unroll
    for (int i = 0; i < 2; i++) {
        int r0 = m0 + warp_m * 32 + i * 16 + (l >> 2);
        #pragma unroll
        for (int n = 0; n < 8; n++) {
            int cl = warp_n * 64 + n * 8 + (l & 3) * 2;
            float s0 = sS[cl], s1 = sS[cl + 1];
            float2 o0 = make_float2(acc[i][n][0] * s0, acc[i][n][1] * s1);
            float2 o1 = make_float2(acc[i][n][2] * s0, acc[i][n][3] * s1);
            *(float2*)(out + (size_t)r0 * 4096 + n0 + cl) = o0;
            *(float2*)(out + (size_t)(r0 + 8) * 4096 + n0 + cl) = o1;
        }
    }
}

// ---------------- launcher ----------------
extern "C" void kernel_launch(void* const* d_in, const int* in_sizes, int n_in,
                              void* d_out, int out_size) {
    const float* x      = (const float*)d_in[0];
    const float* signs  = (const float*)d_in[1];
    const float* scale  = (const float*)d_in[2];
    const float* lora_A = (const float*)d_in[3];
    const float* lora_B = (const float*)d_in[4];
    float* out = (float*)d_out;

    x_h_kernel<<<16384, 256>>>(x);
    s_h_kernel<<<8192, 256>>>(signs);
    lora_t_kernel<<<128, 256>>>(x, lora_A);
    t_pack_kernel<<<32, 256>>>();
    b_pack_kernel<<<16, 256>>>(lora_B, scale);

    cudaFuncSetAttribute(lora_gemm_kernel,
                         cudaFuncAttributeMaxDynamicSharedMemorySize, SMEM_TOTAL);
    lora_gemm_kernel<<<dim3(32, 64), 256, SMEM_TOTAL>>>(scale, out);
}